// round 9
// baseline (speedup 1.0000x reference)
#include <cuda_runtime.h>
#include <cuda_fp16.h>
#include <cstdint>

// Problem shape (fixed)
#define EXPERTS 16
#define MTOK    2048
#define DIM     1024
#define HID     4096

// GEMM tiling
#define BM 128
#define BN 128
#define BK 64                            // fp16: 64 k per 16KB panel (128B rows)
#define PANELH 8192                      // halfs per 128x64 panel (16KB)
#define STG_B  (2*PANELH*2)              // A + B panel bytes per stage (32KB)
#define SMEM_BYTES (3*STG_B)             // 98304 -> 2 CTAs/SM

// Scratch (allocation-free rule: __device__ globals)
__device__ __half g_xp [(size_t)EXPERTS*MTOK*DIM];   // x panels    [e][mb=16][kb=16]
__device__ __half g_w1p[(size_t)EXPERTS*DIM*HID];    // w1^T panels [e][nb=32][kb=16]
__device__ __half g_w2p[(size_t)EXPERTS*HID*DIM];    // w2^T panels [e][nb=8][kb=64]
__device__ __half g_hid[(size_t)EXPERTS*MTOK*HID];   // hidden panels [e][mb=16][kb=64]

// Panel layout (A and B identical): 128 rows x 64 k fp16, 128B per row.
// Row r, 16B group h (k = 8h..8h+7, linear) at byte  r*128 + ((h ^ (r&7))<<4).

// ---------------- helpers ----------------
__device__ __forceinline__ float gelu_exact(float x){
    return 0.5f*x*(1.0f+erff(x*0.70710678118654752440f));
}
__device__ __forceinline__ void cp16(void* smem, const void* gmem){
    unsigned s = (unsigned)__cvta_generic_to_shared(smem);
    asm volatile("cp.async.cg.shared.global [%0], [%1], 16;\n" :: "r"(s), "l"(gmem));
}
__device__ __forceinline__ uint32_t h2u(float a, float b){
    __half2 h = __floats2half2_rn(a, b);
    return *reinterpret_cast<uint32_t*>(&h);
}
__device__ __forceinline__ void ldsm4(uint32_t (&r)[4], uint32_t addr){
    asm volatile("ldmatrix.sync.aligned.m8n8.x4.shared.b16 {%0,%1,%2,%3}, [%4];"
        : "=r"(r[0]), "=r"(r[1]), "=r"(r[2]), "=r"(r[3]) : "r"(addr));
}

// ---------------- pre-pass: x -> fp16 linear-group panels ----------------
__global__ __launch_bounds__(256) void pack_x(const float* __restrict__ X, __half* __restrict__ P){
    const int e = blockIdx.z, mb = blockIdx.y, kb = blockIdx.x;   // 128 rows x 64 k
    char* panel = (char*)(P + (((size_t)e*16 + mb)*(DIM/64) + kb)*(size_t)PANELH);
    #pragma unroll
    for (int i=0;i<4;i++){
        int idx = threadIdx.x + i*256;     // 1024 groups
        int m = idx>>3, h = idx&7;
        const float* s = X + ((size_t)e*MTOK + (size_t)mb*128 + m)*DIM + kb*64 + h*8;
        float4 v0 = *(const float4*)s;
        float4 v1 = *(const float4*)(s+4);
        uint4 o = make_uint4(h2u(v0.x,v0.y), h2u(v0.z,v0.w),
                             h2u(v1.x,v1.y), h2u(v1.z,v1.w));
        uint32_t off = (uint32_t)(m*128) + (uint32_t)((h ^ (m&7))<<4);
        *(uint4*)(panel + off) = o;
    }
}

// ---- pre-pass: W[K,N] -> fp16 W^T linear-group panels [e][nb][kb] ----
__global__ __launch_bounds__(256) void pack_w(const float* __restrict__ W, __half* __restrict__ P,
                                              int K, int N){
    __shared__ float ts[64][132];
    const int e = blockIdx.z, nb = blockIdx.x, kb = blockIdx.y;   // 64 k x 128 n
    const float* src = W + ((size_t)e*K + (size_t)kb*64)*N + (size_t)nb*128;
    #pragma unroll
    for (int i=0;i<8;i++){
        int idx = threadIdx.x + i*256;     // 2048 float4
        int r = idx>>5, c4 = idx&31;
        float4 v = *(const float4*)(src + (size_t)r*N + c4*4);
        ts[r][c4*4+0]=v.x; ts[r][c4*4+1]=v.y; ts[r][c4*4+2]=v.z; ts[r][c4*4+3]=v.w;
    }
    __syncthreads();
    char* panel = (char*)(P + (((size_t)e*(N>>7) + nb)*(size_t)(K>>6) + kb)*(size_t)PANELH);
    #pragma unroll
    for (int i=0;i<4;i++){
        int idx = threadIdx.x + i*256;     // 1024 groups
        int n = idx>>3, h = idx&7;
        float f[8];
        #pragma unroll
        for (int j=0;j<8;j++) f[j] = ts[h*8+j][n];
        uint4 o = make_uint4(h2u(f[0],f[1]), h2u(f[2],f[3]),
                             h2u(f[4],f[5]), h2u(f[6],f[7]));
        uint32_t off = (uint32_t)(n*128) + (uint32_t)((h ^ (n&7))<<4);
        *(uint4*)(panel + off) = o;
    }
}

// ---------------- main GEMM: mma.sync fp16 m16n8k16, ldmatrix frags ----------------
template<bool G1>
__global__ void __launch_bounds__(256,2)
gemm_t(const __half* __restrict__ Ap, const __half* __restrict__ Bp,
       const float* __restrict__ bias, void* __restrict__ OutV, int KT)
{
    extern __shared__ float sm[];
    const uint32_t smemBase = (uint32_t)__cvta_generic_to_shared(sm);
    const int tid = threadIdx.x, warp = tid>>5, lane = tid&31;
    const int g = lane>>2, t = lane&3;
    const int lan7 = lane&7;
    const int wm = (warp&3)*32, wn = (warp>>2)*64;
    const int bx = blockIdx.x, by = blockIdx.y, e = blockIdx.z;
    const int NB = gridDim.x;

    const __half* Ab0 = Ap + ((size_t)e*gridDim.y + by)*(size_t)KT*PANELH;
    const __half* Bb0 = Bp + ((size_t)e*NB + bx)*(size_t)KT*PANELH;

    auto loadStage = [&](int slot, int s){
        char* dst = (char*)sm + slot*STG_B;
        const char* a = (const char*)(Ab0 + (size_t)s*PANELH);
        const char* b = (const char*)(Bb0 + (size_t)s*PANELH);
        #pragma unroll
        for (int j=0;j<4;j++){ int idx = tid + j*256; cp16(dst + idx*16, a + idx*16); }
        #pragma unroll
        for (int j=0;j<4;j++){ int idx = tid + j*256; cp16(dst + 16384 + idx*16, b + idx*16); }
    };

    // ldmatrix per-thread row byte offsets (within panel)
    const int kselA = (lane>>4)&1;
    uint32_t aRow[2];
    #pragma unroll
    for (int im=0;im<2;im++)
        aRow[im] = (uint32_t)((wm + im*16 + lan7 + ((lane>>3)&1)*8) * 128);
    const int kselB = (lane>>3)&1;
    const uint32_t bRow0 = (uint32_t)((wn + lan7 + ((lane>>4)&1)*8) * 128);

    // precomputed per-ck swizzled group offsets
    uint32_t gA[4], gB[4];
    #pragma unroll
    for (int ck=0;ck<4;ck++){
        gA[ck] = (uint32_t)(((ck*2 + kselA) ^ lan7) << 4);
        gB[ck] = (uint32_t)(((ck*2 + kselB) ^ lan7) << 4);
    }

    float c[2][8][4];
    #pragma unroll
    for (int im=0;im<2;im++)
        #pragma unroll
        for (int in=0;in<8;in++)
            #pragma unroll
            for (int r=0;r<4;r++) c[im][in][r]=0.0f;

    uint32_t aF[2][2][4], bF[2][4][4];
    auto ldFrags = [&](uint32_t Ab, uint32_t Bb, int ck, int buf){
        ldsm4(aF[buf][0], Ab + aRow[0] + gA[ck]);
        ldsm4(aF[buf][1], Ab + aRow[1] + gA[ck]);
        #pragma unroll
        for (int p=0;p<4;p++)
            ldsm4(bF[buf][p], Bb + bRow0 + (uint32_t)(p*2048) + gB[ck]);
    };
    auto domma = [&](int buf){
        #pragma unroll
        for (int im=0;im<2;im++)
            #pragma unroll
            for (int in=0;in<8;in++){
                const uint32_t b0 = bF[buf][in>>1][(in&1)*2];
                const uint32_t b1 = bF[buf][in>>1][(in&1)*2+1];
                asm volatile(
                    "mma.sync.aligned.m16n8k16.row.col.f32.f16.f16.f32 "
                    "{%0,%1,%2,%3}, {%4,%5,%6,%7}, {%8,%9}, {%0,%1,%2,%3};"
                    : "+f"(c[im][in][0]), "+f"(c[im][in][1]),
                      "+f"(c[im][in][2]), "+f"(c[im][in][3])
                    : "r"(aF[buf][im][0]), "r"(aF[buf][im][1]),
                      "r"(aF[buf][im][2]), "r"(aF[buf][im][3]),
                      "r"(b0), "r"(b1));
            }
    };

    loadStage(0,0); asm volatile("cp.async.commit_group;\n");
    loadStage(1,1); asm volatile("cp.async.commit_group;\n");

    #pragma unroll 1
    for (int s=0; s<KT; s++){
        asm volatile("cp.async.wait_group 1;\n");
        __syncthreads();
        if (s+2 < KT) loadStage((s+2)%3, s+2);
        asm volatile("cp.async.commit_group;\n");   // always commit -> exact accounting

        const uint32_t Ab = smemBase + (s%3)*STG_B;
        const uint32_t Bb = Ab + 16384;

        ldFrags(Ab, Bb, 0, 0);
        #pragma unroll
        for (int ck=0; ck<4; ck++){
            if (ck < 3) ldFrags(Ab, Bb, ck+1, (ck+1)&1);  // in-flight during ck's HMMAs
            domma(ck&1);
        }
    }
    asm volatile("cp.async.wait_group 0;\n");

    if (G1){
        // stage bias+gelu through smem, emit hidden as fp16 linear-group panels
        __half* Out = (__half*)OutV;
        __syncthreads();
        float* stage = sm;                  // [128][132]
        float bv[8][2];
        #pragma unroll
        for (int in=0;in<8;in++){
            int col = bx*BN + wn + in*8 + 2*t;
            bv[in][0] = __ldg(&bias[col]);
            bv[in][1] = __ldg(&bias[col+1]);
        }
        #pragma unroll
        for (int im=0;im<2;im++)
            #pragma unroll
            for (int rh=0;rh<2;rh++){
                int row = wm + im*16 + g + rh*8;
                #pragma unroll
                for (int in=0;in<8;in++){
                    int col = wn + in*8 + 2*t;
                    float v0 = gelu_exact(c[im][in][rh*2+0] + bv[in][0]);
                    float v1 = gelu_exact(c[im][in][rh*2+1] + bv[in][1]);
                    *(float2*)&stage[row*132 + col] = make_float2(v0, v1);
                }
            }
        __syncthreads();
        // pack 128 rows x 128 n -> 2 k-blocks of 64 (k-dim of GEMM2)
        const int KT2 = HID/64;
        #pragma unroll
        for (int i=0;i<8;i++){
            int p = tid + i*256;            // 2048 groups
            int m = p>>4, r = p&15;
            int kbl = r>>3, h = r&7;
            const float* srow = &stage[m*132 + kbl*64 + h*8];
            uint4 v = make_uint4(h2u(srow[0],srow[1]), h2u(srow[2],srow[3]),
                                 h2u(srow[4],srow[5]), h2u(srow[6],srow[7]));
            char* panel = (char*)(Out + (((size_t)e*16 + by)*KT2 + (bx*2 + kbl))*(size_t)PANELH);
            uint32_t off = (uint32_t)(m*128) + (uint32_t)((h ^ (m&7))<<4);
            *(uint4*)(panel + off) = v;
        }
    } else {
        float* Out = (float*)OutV;
        const int Nout = NB*BN;
        #pragma unroll
        for (int im=0;im<2;im++)
            #pragma unroll
            for (int rh=0;rh<2;rh++){
                int row = by*BM + wm + im*16 + g + rh*8;
                #pragma unroll
                for (int in=0;in<8;in++){
                    int col = bx*BN + wn + in*8 + 2*t;
                    float v0 = c[im][in][rh*2+0] + __ldg(&bias[col]);
                    float v1 = c[im][in][rh*2+1] + __ldg(&bias[col+1]);
                    *reinterpret_cast<float2*>(&Out[((size_t)e*MTOK + row)*Nout + col]) =
                        make_float2(v0, v1);
                }
            }
    }
}

// ---------------- host ----------------
extern "C" void kernel_launch(void* const* d_in, const int* in_sizes, int n_in,
                              void* d_out, int out_size)
{
    const float* x  = (const float*)d_in[0];   // [E, 2048, 1024]
    const float* w1 = (const float*)d_in[1];   // [E, 1024, 4096]
    const float* w2 = (const float*)d_in[2];   // [E, 4096, 1024]
    const float* b1 = (const float*)d_in[3];   // [4096]
    const float* b2 = (const float*)d_in[4];   // [1024]
    float* out = (float*)d_out;                // [E, 2048, 1024]

    __half *xp, *w1p, *w2p, *hid;
    cudaGetSymbolAddress((void**)&xp,  g_xp);
    cudaGetSymbolAddress((void**)&w1p, g_w1p);
    cudaGetSymbolAddress((void**)&w2p, g_w2p);
    cudaGetSymbolAddress((void**)&hid, g_hid);

    cudaFuncSetAttribute(gemm_t<true>,  cudaFuncAttributeMaxDynamicSharedMemorySize, SMEM_BYTES);
    cudaFuncSetAttribute(gemm_t<false>, cudaFuncAttributeMaxDynamicSharedMemorySize, SMEM_BYTES);

    // pre-pass: fp16 conversion + panelization
    pack_x<<<dim3(DIM/64, MTOK/128, EXPERTS), 256>>>(x, xp);
    pack_w<<<dim3(HID/128, DIM/64, EXPERTS), 256>>>(w1, w1p, DIM, HID);
    pack_w<<<dim3(DIM/128, HID/64, EXPERTS), 256>>>(w2, w2p, HID, DIM);

    // GEMM1 + exact GELU -> hidden fp16 panels; GEMM2 -> row-major fp32 out
    gemm_t<true ><<<dim3(HID/BN, MTOK/BM, EXPERTS), 256, SMEM_BYTES>>>(xp, w1p, b1, hid, DIM/64);
    gemm_t<false><<<dim3(DIM/BN, MTOK/BM, EXPERTS), 256, SMEM_BYTES>>>(hid, w2p, b2, out, HID/64);
}

// round 11
// speedup vs baseline: 1.0114x; 1.0114x over previous
#include <cuda_runtime.h>
#include <cuda_fp16.h>
#include <cstdint>

// Problem shape (fixed)
#define EXPERTS 16
#define MTOK    2048
#define DIM     1024
#define HID     4096

// GEMM tiling
#define BM 128
#define BN 128
#define BK 64                            // fp16: 64 k per 16KB panel (128B rows)
#define PANELH 8192                      // halfs per 128x64 panel (16KB)
#define STG_B  (2*PANELH*2)              // A + B panel bytes per stage (32KB)
#define SMEM_BYTES (3*STG_B)             // 98304 -> 2 CTAs/SM

// Scratch (allocation-free rule: __device__ globals)
__device__ __half g_xp [(size_t)EXPERTS*MTOK*DIM];   // x panels    [e][mb=16][kb=16]
__device__ __half g_w1p[(size_t)EXPERTS*DIM*HID];    // w1^T panels [e][nb=32][kb=16]
__device__ __half g_w2p[(size_t)EXPERTS*HID*DIM];    // w2^T panels [e][nb=8][kb=64]
__device__ __half g_hid[(size_t)EXPERTS*MTOK*HID];   // hidden panels [e][mb=16][kb=64]

// Panel layout (A and B identical): 128 rows x 64 k fp16, 128B per row.
// Row r, 16B group h (k = 8h..8h+7, linear) at byte  r*128 + ((h ^ (r&7))<<4).

// ---------------- helpers ----------------
__device__ __forceinline__ float gelu_exact(float x){
    return 0.5f*x*(1.0f+erff(x*0.70710678118654752440f));
}
__device__ __forceinline__ void cp16(void* smem, const void* gmem){
    unsigned s = (unsigned)__cvta_generic_to_shared(smem);
    asm volatile("cp.async.cg.shared.global [%0], [%1], 16;\n" :: "r"(s), "l"(gmem));
}
__device__ __forceinline__ uint32_t h2u(float a, float b){
    __half2 h = __floats2half2_rn(a, b);
    return *reinterpret_cast<uint32_t*>(&h);
}
__device__ __forceinline__ void ldsm4(uint32_t (&r)[4], uint32_t addr){
    asm volatile("ldmatrix.sync.aligned.m8n8.x4.shared.b16 {%0,%1,%2,%3}, [%4];"
        : "=r"(r[0]), "=r"(r[1]), "=r"(r[2]), "=r"(r[3]) : "r"(addr));
}

// ---------------- pre-pass: x -> fp16 linear-group panels ----------------
__global__ __launch_bounds__(256) void pack_x(const float* __restrict__ X, __half* __restrict__ P){
    const int e = blockIdx.z, mb = blockIdx.y, kb = blockIdx.x;   // 128 rows x 64 k
    char* panel = (char*)(P + (((size_t)e*16 + mb)*(DIM/64) + kb)*(size_t)PANELH);
    #pragma unroll
    for (int i=0;i<4;i++){
        int idx = threadIdx.x + i*256;     // 1024 groups
        int m = idx>>3, h = idx&7;
        const float* s = X + ((size_t)e*MTOK + (size_t)mb*128 + m)*DIM + kb*64 + h*8;
        float4 v0 = *(const float4*)s;
        float4 v1 = *(const float4*)(s+4);
        uint4 o = make_uint4(h2u(v0.x,v0.y), h2u(v0.z,v0.w),
                             h2u(v1.x,v1.y), h2u(v1.z,v1.w));
        uint32_t off = (uint32_t)(m*128) + (uint32_t)((h ^ (m&7))<<4);
        *(uint4*)(panel + off) = o;
    }
}

// ---- pre-pass: W[K,N] -> fp16 W^T linear-group panels [e][nb][kb] ----
__global__ __launch_bounds__(256) void pack_w(const float* __restrict__ W, __half* __restrict__ P,
                                              int K, int N){
    __shared__ float ts[64][132];
    const int e = blockIdx.z, nb = blockIdx.x, kb = blockIdx.y;   // 64 k x 128 n
    const float* src = W + ((size_t)e*K + (size_t)kb*64)*N + (size_t)nb*128;
    #pragma unroll
    for (int i=0;i<8;i++){
        int idx = threadIdx.x + i*256;     // 2048 float4
        int r = idx>>5, c4 = idx&31;
        float4 v = *(const float4*)(src + (size_t)r*N + c4*4);
        ts[r][c4*4+0]=v.x; ts[r][c4*4+1]=v.y; ts[r][c4*4+2]=v.z; ts[r][c4*4+3]=v.w;
    }
    __syncthreads();
    char* panel = (char*)(P + (((size_t)e*(N>>7) + nb)*(size_t)(K>>6) + kb)*(size_t)PANELH);
    #pragma unroll
    for (int i=0;i<4;i++){
        int idx = threadIdx.x + i*256;     // 1024 groups
        int n = idx>>3, h = idx&7;
        float f[8];
        #pragma unroll
        for (int j=0;j<8;j++) f[j] = ts[h*8+j][n];
        uint4 o = make_uint4(h2u(f[0],f[1]), h2u(f[2],f[3]),
                             h2u(f[4],f[5]), h2u(f[6],f[7]));
        uint32_t off = (uint32_t)(n*128) + (uint32_t)((h ^ (n&7))<<4);
        *(uint4*)(panel + off) = o;
    }
}

// ---------------- main GEMM: mma.sync fp16 m16n8k16, safe cross-barrier prefetch ----------------
template<bool G1>
__global__ void __launch_bounds__(256,2)
gemm_t(const __half* __restrict__ Ap, const __half* __restrict__ Bp,
       const float* __restrict__ bias, void* __restrict__ OutV, int KT)
{
    extern __shared__ float sm[];
    const uint32_t smemBase = (uint32_t)__cvta_generic_to_shared(sm);
    const int tid = threadIdx.x, warp = tid>>5, lane = tid&31;
    const int g = lane>>2, t = lane&3;
    const int lan7 = lane&7;
    const int wm = (warp&3)*32, wn = (warp>>2)*64;
    const int bx = blockIdx.x, by = blockIdx.y, e = blockIdx.z;
    const int NB = gridDim.x;

    const __half* Ab0 = Ap + ((size_t)e*gridDim.y + by)*(size_t)KT*PANELH;
    const __half* Bb0 = Bp + ((size_t)e*NB + bx)*(size_t)KT*PANELH;

    auto loadStage = [&](int slot, int s){
        char* dst = (char*)sm + slot*STG_B;
        const char* a = (const char*)(Ab0 + (size_t)s*PANELH);
        const char* b = (const char*)(Bb0 + (size_t)s*PANELH);
        #pragma unroll
        for (int j=0;j<4;j++){ int idx = tid + j*256; cp16(dst + idx*16, a + idx*16); }
        #pragma unroll
        for (int j=0;j<4;j++){ int idx = tid + j*256; cp16(dst + 16384 + idx*16, b + idx*16); }
    };

    // ldmatrix per-thread row byte offsets (within panel)
    const int kselA = (lane>>4)&1;
    uint32_t aRow[2];
    #pragma unroll
    for (int im=0;im<2;im++)
        aRow[im] = (uint32_t)((wm + im*16 + lan7 + ((lane>>3)&1)*8) * 128);
    const int kselB = (lane>>3)&1;
    const uint32_t bRow0 = (uint32_t)((wn + lan7 + ((lane>>4)&1)*8) * 128);

    // precomputed per-ck swizzled group offsets
    uint32_t gA[4], gB[4];
    #pragma unroll
    for (int ck=0;ck<4;ck++){
        gA[ck] = (uint32_t)(((ck*2 + kselA) ^ lan7) << 4);
        gB[ck] = (uint32_t)(((ck*2 + kselB) ^ lan7) << 4);
    }

    float c[2][8][4];
    #pragma unroll
    for (int im=0;im<2;im++)
        #pragma unroll
        for (int in=0;in<8;in++)
            #pragma unroll
            for (int r=0;r<4;r++) c[im][in][r]=0.0f;

    uint32_t aF[2][2][4], bF[2][4][4];
    auto ldFrags = [&](uint32_t Ab, uint32_t Bb, int ck, int buf){
        ldsm4(aF[buf][0], Ab + aRow[0] + gA[ck]);
        ldsm4(aF[buf][1], Ab + aRow[1] + gA[ck]);
        #pragma unroll
        for (int p=0;p<4;p++)
            ldsm4(bF[buf][p], Bb + bRow0 + (uint32_t)(p*2048) + gB[ck]);
    };
    auto domma = [&](int buf){
        #pragma unroll
        for (int im=0;im<2;im++)
            #pragma unroll
            for (int in=0;in<8;in++){
                const uint32_t b0 = bF[buf][in>>1][(in&1)*2];
                const uint32_t b1 = bF[buf][in>>1][(in&1)*2+1];
                asm volatile(
                    "mma.sync.aligned.m16n8k16.row.col.f32.f16.f16.f32 "
                    "{%0,%1,%2,%3}, {%4,%5,%6,%7}, {%8,%9}, {%0,%1,%2,%3};"
                    : "+f"(c[im][in][0]), "+f"(c[im][in][1]),
                      "+f"(c[im][in][2]), "+f"(c[im][in][3])
                    : "r"(aF[buf][im][0]), "r"(aF[buf][im][1]),
                      "r"(aF[buf][im][2]), "r"(aF[buf][im][3]),
                      "r"(b0), "r"(b1));
            }
    };

    // prologue: stage 0+1 in flight; stage 0 resident + visible; ck0 frags in buf0
    loadStage(0,0); asm volatile("cp.async.commit_group;\n");
    loadStage(1,1); asm volatile("cp.async.commit_group;\n");
    asm volatile("cp.async.wait_group 1;\n");
    __syncthreads();
    ldFrags(smemBase, smemBase + 16384, 0, 0);

    #pragma unroll 1
    for (int s=0; s<KT; s++){
        const uint32_t Ab_s = smemBase + (s%3)*STG_B;
        const uint32_t Bb_s = Ab_s + 16384;

        // ck0..ck2: prefetch ck+1 within stage, then mma
        #pragma unroll
        for (int ck=0; ck<3; ck++){
            ldFrags(Ab_s, Bb_s, ck+1, (ck+1)&1);
            domma(ck&1);
        }

        // stage boundary: drain OUR groups, then full barrier => everyone's copies
        // for stage s+1 are globally visible (this ordering is what r10 got wrong).
        asm volatile("cp.async.wait_group 0;\n");
        __syncthreads();

        if (s+1 < KT){
            const uint32_t Ab_n = smemBase + ((s+1)%3)*STG_B;
            ldFrags(Ab_n, Ab_n + 16384, 0, 0);    // next stage ck0 -> buf0 (race-free)
        }
        domma(1);                                  // ck3 from buf1 covers prefetch latency

        if (s+2 < KT) loadStage((s+2)%3, s+2);     // slot (s-1)%3: reads ended pre-barrier
        asm volatile("cp.async.commit_group;\n");  // always commit -> exact accounting
    }
    asm volatile("cp.async.wait_group 0;\n");

    if (G1){
        // stage bias+gelu through smem, emit hidden as fp16 linear-group panels
        __half* Out = (__half*)OutV;
        __syncthreads();
        float* stage = sm;                  // [128][132]
        float bv[8][2];
        #pragma unroll
        for (int in=0;in<8;in++){
            int col = bx*BN + wn + in*8 + 2*t;
            bv[in][0] = __ldg(&bias[col]);
            bv[in][1] = __ldg(&bias[col+1]);
        }
        #pragma unroll
        for (int im=0;im<2;im++)
            #pragma unroll
            for (int rh=0;rh<2;rh++){
                int row = wm + im*16 + g + rh*8;
                #pragma unroll
                for (int in=0;in<8;in++){
                    int col = wn + in*8 + 2*t;
                    float v0 = gelu_exact(c[im][in][rh*2+0] + bv[in][0]);
                    float v1 = gelu_exact(c[im][in][rh*2+1] + bv[in][1]);
                    *(float2*)&stage[row*132 + col] = make_float2(v0, v1);
                }
            }
        __syncthreads();
        // pack 128 rows x 128 n -> 2 k-blocks of 64 (k-dim of GEMM2)
        const int KT2 = HID/64;
        #pragma unroll
        for (int i=0;i<8;i++){
            int p = tid + i*256;            // 2048 groups
            int m = p>>4, r = p&15;
            int kbl = r>>3, h = r&7;
            const float* srow = &stage[m*132 + kbl*64 + h*8];
            uint4 v = make_uint4(h2u(srow[0],srow[1]), h2u(srow[2],srow[3]),
                                 h2u(srow[4],srow[5]), h2u(srow[6],srow[7]));
            char* panel = (char*)(Out + (((size_t)e*16 + by)*KT2 + (bx*2 + kbl))*(size_t)PANELH);
            uint32_t off = (uint32_t)(m*128) + (uint32_t)((h ^ (m&7))<<4);
            *(uint4*)(panel + off) = v;
        }
    } else {
        float* Out = (float*)OutV;
        const int Nout = NB*BN;
        #pragma unroll
        for (int im=0;im<2;im++)
            #pragma unroll
            for (int rh=0;rh<2;rh++){
                int row = by*BM + wm + im*16 + g + rh*8;
                #pragma unroll
                for (int in=0;in<8;in++){
                    int col = bx*BN + wn + in*8 + 2*t;
                    float v0 = c[im][in][rh*2+0] + __ldg(&bias[col]);
                    float v1 = c[im][in][rh*2+1] + __ldg(&bias[col+1]);
                    *reinterpret_cast<float2*>(&Out[((size_t)e*MTOK + row)*Nout + col]) =
                        make_float2(v0, v1);
                }
            }
    }
}

// ---------------- host ----------------
extern "C" void kernel_launch(void* const* d_in, const int* in_sizes, int n_in,
                              void* d_out, int out_size)
{
    const float* x  = (const float*)d_in[0];   // [E, 2048, 1024]
    const float* w1 = (const float*)d_in[1];   // [E, 1024, 4096]
    const float* w2 = (const float*)d_in[2];   // [E, 4096, 1024]
    const float* b1 = (const float*)d_in[3];   // [4096]
    const float* b2 = (const float*)d_in[4];   // [1024]
    float* out = (float*)d_out;                // [E, 2048, 1024]

    __half *xp, *w1p, *w2p, *hid;
    cudaGetSymbolAddress((void**)&xp,  g_xp);
    cudaGetSymbolAddress((void**)&w1p, g_w1p);
    cudaGetSymbolAddress((void**)&w2p, g_w2p);
    cudaGetSymbolAddress((void**)&hid, g_hid);

    cudaFuncSetAttribute(gemm_t<true>,  cudaFuncAttributeMaxDynamicSharedMemorySize, SMEM_BYTES);
    cudaFuncSetAttribute(gemm_t<false>, cudaFuncAttributeMaxDynamicSharedMemorySize, SMEM_BYTES);

    // pre-pass: fp16 conversion + panelization
    pack_x<<<dim3(DIM/64, MTOK/128, EXPERTS), 256>>>(x, xp);
    pack_w<<<dim3(HID/128, DIM/64, EXPERTS), 256>>>(w1, w1p, DIM, HID);
    pack_w<<<dim3(DIM/128, HID/64, EXPERTS), 256>>>(w2, w2p, HID, DIM);

    // GEMM1 + exact GELU -> hidden fp16 panels; GEMM2 -> row-major fp32 out
    gemm_t<true ><<<dim3(HID/BN, MTOK/BM, EXPERTS), 256, SMEM_BYTES>>>(xp, w1p, b1, hid, DIM/64);
    gemm_t<false><<<dim3(DIM/BN, MTOK/BM, EXPERTS), 256, SMEM_BYTES>>>(hid, w2p, b2, out, HID/64);
}

// round 13
// speedup vs baseline: 1.0369x; 1.0253x over previous
#include <cuda_runtime.h>
#include <cuda_fp16.h>
#include <cstdint>

// Problem shape (fixed)
#define EXPERTS 16
#define MTOK    2048
#define DIM     1024
#define HID     4096

// GEMM tiling: CTA 128x128, 4 warps, warp tile 64x64
#define BM 128
#define BN 128
#define BK 64                            // fp16: 64 k per 16KB panel (128B rows)
#define NTHR 128
#define PANELH 8192                      // halfs per 128x64 panel (16KB)
#define STG_B  (2*PANELH*2)              // A + B panel bytes per stage (32KB)
#define SMEM_BYTES (3*STG_B)             // 98304 -> 2 CTAs/SM

// Scratch (allocation-free rule: __device__ globals)
__device__ __half g_xp [(size_t)EXPERTS*MTOK*DIM];   // x panels    [e][mb=16][kb=16]
__device__ __half g_w1p[(size_t)EXPERTS*DIM*HID];    // w1^T panels [e][nb=32][kb=16]
__device__ __half g_w2p[(size_t)EXPERTS*HID*DIM];    // w2^T panels [e][nb=8][kb=64]
__device__ __half g_hid[(size_t)EXPERTS*MTOK*HID];   // hidden panels [e][mb=16][kb=64]

// Panel layout (A and B identical): 128 rows x 64 k fp16, 128B per row.
// Row r, 16B group h (k = 8h..8h+7, linear) at byte  r*128 + ((h ^ (r&7))<<4).

// ---------------- helpers ----------------
__device__ __forceinline__ float gelu_exact(float x){
    return 0.5f*x*(1.0f+erff(x*0.70710678118654752440f));
}
__device__ __forceinline__ void cp16(void* smem, const void* gmem){
    unsigned s = (unsigned)__cvta_generic_to_shared(smem);
    asm volatile("cp.async.cg.shared.global [%0], [%1], 16;\n" :: "r"(s), "l"(gmem));
}
__device__ __forceinline__ uint32_t h2u(float a, float b){
    __half2 h = __floats2half2_rn(a, b);
    return *reinterpret_cast<uint32_t*>(&h);
}
__device__ __forceinline__ void ldsm4(uint32_t (&r)[4], uint32_t addr){
    asm volatile("ldmatrix.sync.aligned.m8n8.x4.shared.b16 {%0,%1,%2,%3}, [%4];"
        : "=r"(r[0]), "=r"(r[1]), "=r"(r[2]), "=r"(r[3]) : "r"(addr));
}

// ---------------- pre-pass: x -> fp16 linear-group panels ----------------
__global__ __launch_bounds__(256) void pack_x(const float* __restrict__ X, __half* __restrict__ P){
    const int e = blockIdx.z, mb = blockIdx.y, kb = blockIdx.x;   // 128 rows x 64 k
    char* panel = (char*)(P + (((size_t)e*16 + mb)*(DIM/64) + kb)*(size_t)PANELH);
    #pragma unroll
    for (int i=0;i<4;i++){
        int idx = threadIdx.x + i*256;     // 1024 groups
        int m = idx>>3, h = idx&7;
        const float* s = X + ((size_t)e*MTOK + (size_t)mb*128 + m)*DIM + kb*64 + h*8;
        float4 v0 = *(const float4*)s;
        float4 v1 = *(const float4*)(s+4);
        uint4 o = make_uint4(h2u(v0.x,v0.y), h2u(v0.z,v0.w),
                             h2u(v1.x,v1.y), h2u(v1.z,v1.w));
        uint32_t off = (uint32_t)(m*128) + (uint32_t)((h ^ (m&7))<<4);
        *(uint4*)(panel + off) = o;
    }
}

// ---- pre-pass: W[K,N] -> fp16 W^T linear-group panels [e][nb][kb] ----
__global__ __launch_bounds__(256) void pack_w(const float* __restrict__ W, __half* __restrict__ P,
                                              int K, int N){
    __shared__ float ts[64][132];
    const int e = blockIdx.z, nb = blockIdx.x, kb = blockIdx.y;   // 64 k x 128 n
    const float* src = W + ((size_t)e*K + (size_t)kb*64)*N + (size_t)nb*128;
    #pragma unroll
    for (int i=0;i<8;i++){
        int idx = threadIdx.x + i*256;     // 2048 float4
        int r = idx>>5, c4 = idx&31;
        float4 v = *(const float4*)(src + (size_t)r*N + c4*4);
        ts[r][c4*4+0]=v.x; ts[r][c4*4+1]=v.y; ts[r][c4*4+2]=v.z; ts[r][c4*4+3]=v.w;
    }
    __syncthreads();
    char* panel = (char*)(P + (((size_t)e*(N>>7) + nb)*(size_t)(K>>6) + kb)*(size_t)PANELH);
    #pragma unroll
    for (int i=0;i<4;i++){
        int idx = threadIdx.x + i*256;     // 1024 groups
        int n = idx>>3, h = idx&7;
        float f[8];
        #pragma unroll
        for (int j=0;j<8;j++) f[j] = ts[h*8+j][n];
        uint4 o = make_uint4(h2u(f[0],f[1]), h2u(f[2],f[3]),
                             h2u(f[4],f[5]), h2u(f[6],f[7]));
        uint32_t off = (uint32_t)(n*128) + (uint32_t)((h ^ (n&7))<<4);
        *(uint4*)(panel + off) = o;
    }
}

// ---------------- main GEMM: mma.sync fp16 m16n8k16, 64x64 warp tiles ----------------
template<bool G1>
__global__ void __launch_bounds__(NTHR,2)
gemm_t(const __half* __restrict__ Ap, const __half* __restrict__ Bp,
       const float* __restrict__ bias, void* __restrict__ OutV, int KT)
{
    extern __shared__ float sm[];
    const uint32_t smemBase = (uint32_t)__cvta_generic_to_shared(sm);
    const int tid = threadIdx.x, warp = tid>>5, lane = tid&31;
    const int g = lane>>2, t = lane&3;
    const int lan7 = lane&7;
    const int wm = (warp&1)*64, wn = (warp>>1)*64;   // 2x2 warp grid, 64x64 tiles
    const int bx = blockIdx.x, by = blockIdx.y, e = blockIdx.z;
    const int NB = gridDim.x;

    const __half* Ab0 = Ap + ((size_t)e*gridDim.y + by)*(size_t)KT*PANELH;
    const __half* Bb0 = Bp + ((size_t)e*NB + bx)*(size_t)KT*PANELH;

    auto loadStage = [&](int slot, int s){
        char* dst = (char*)sm + slot*STG_B;
        const char* a = (const char*)(Ab0 + (size_t)s*PANELH);
        const char* b = (const char*)(Bb0 + (size_t)s*PANELH);
        #pragma unroll
        for (int j=0;j<8;j++){ int idx = tid + j*NTHR; cp16(dst + idx*16, a + idx*16); }
        #pragma unroll
        for (int j=0;j<8;j++){ int idx = tid + j*NTHR; cp16(dst + 16384 + idx*16, b + idx*16); }
    };

    // ldmatrix per-thread row byte offsets (within panel)
    const int kselA = (lane>>4)&1;
    uint32_t aRow[4];
    #pragma unroll
    for (int im=0;im<4;im++)
        aRow[im] = (uint32_t)((wm + im*16 + lan7 + ((lane>>3)&1)*8) * 128);
    const int kselB = (lane>>3)&1;
    const uint32_t bRow0 = (uint32_t)((wn + lan7 + ((lane>>4)&1)*8) * 128);

    // precomputed per-ck swizzled group offsets
    uint32_t gA[4], gB[4];
    #pragma unroll
    for (int ck=0;ck<4;ck++){
        gA[ck] = (uint32_t)(((ck*2 + kselA) ^ lan7) << 4);
        gB[ck] = (uint32_t)(((ck*2 + kselB) ^ lan7) << 4);
    }

    float c[4][8][4];
    #pragma unroll
    for (int im=0;im<4;im++)
        #pragma unroll
        for (int in=0;in<8;in++)
            #pragma unroll
            for (int r=0;r<4;r++) c[im][in][r]=0.0f;

    uint32_t aF[2][4][4], bF[2][4][4];
    auto ldFrags = [&](uint32_t Ab, uint32_t Bb, int ck, int buf){
        #pragma unroll
        for (int im=0;im<4;im++)
            ldsm4(aF[buf][im], Ab + aRow[im] + gA[ck]);
        #pragma unroll
        for (int p=0;p<4;p++)
            ldsm4(bF[buf][p], Bb + bRow0 + (uint32_t)(p*2048) + gB[ck]);
    };
    auto domma = [&](int buf){
        #pragma unroll
        for (int im=0;im<4;im++)
            #pragma unroll
            for (int in=0;in<8;in++){
                const uint32_t b0 = bF[buf][in>>1][(in&1)*2];
                const uint32_t b1 = bF[buf][in>>1][(in&1)*2+1];
                asm volatile(
                    "mma.sync.aligned.m16n8k16.row.col.f32.f16.f16.f32 "
                    "{%0,%1,%2,%3}, {%4,%5,%6,%7}, {%8,%9}, {%0,%1,%2,%3};"
                    : "+f"(c[im][in][0]), "+f"(c[im][in][1]),
                      "+f"(c[im][in][2]), "+f"(c[im][in][3])
                    : "r"(aF[buf][im][0]), "r"(aF[buf][im][1]),
                      "r"(aF[buf][im][2]), "r"(aF[buf][im][3]),
                      "r"(b0), "r"(b1));
            }
    };

    loadStage(0,0); asm volatile("cp.async.commit_group;\n");
    loadStage(1,1); asm volatile("cp.async.commit_group;\n");

    #pragma unroll 1
    for (int s=0; s<KT; s++){
        asm volatile("cp.async.wait_group 1;\n");
        __syncthreads();
        if (s+2 < KT) loadStage((s+2)%3, s+2);
        asm volatile("cp.async.commit_group;\n");   // always commit -> exact accounting

        const uint32_t Ab = smemBase + (s%3)*STG_B;
        const uint32_t Bb = Ab + 16384;

        ldFrags(Ab, Bb, 0, 0);
        #pragma unroll
        for (int ck=0; ck<4; ck++){
            if (ck < 3) ldFrags(Ab, Bb, ck+1, (ck+1)&1);  // in flight during ck's HMMAs
            domma(ck&1);
        }
    }
    asm volatile("cp.async.wait_group 0;\n");

    if (G1){
        // stage bias+gelu through smem, emit hidden as fp16 linear-group panels
        __half* Out = (__half*)OutV;
        __syncthreads();
        float* stage = sm;                  // [128][132]
        float bv[8][2];
        #pragma unroll
        for (int in=0;in<8;in++){
            int col = bx*BN + wn + in*8 + 2*t;
            bv[in][0] = __ldg(&bias[col]);
            bv[in][1] = __ldg(&bias[col+1]);
        }
        #pragma unroll
        for (int im=0;im<4;im++)
            #pragma unroll
            for (int rh=0;rh<2;rh++){
                int row = wm + im*16 + g + rh*8;
                #pragma unroll
                for (int in=0;in<8;in++){
                    int col = wn + in*8 + 2*t;
                    float v0 = gelu_exact(c[im][in][rh*2+0] + bv[in][0]);
                    float v1 = gelu_exact(c[im][in][rh*2+1] + bv[in][1]);
                    *(float2*)&stage[row*132 + col] = make_float2(v0, v1);
                }
            }
        __syncthreads();
        // pack 128 rows x 128 n -> 2 k-blocks of 64 (k-dim of GEMM2)
        const int KT2 = HID/64;
        #pragma unroll
        for (int i=0;i<16;i++){
            int p = tid + i*NTHR;           // 2048 groups
            int m = p>>4, r = p&15;
            int kbl = r>>3, h = r&7;
            const float* srow = &stage[m*132 + kbl*64 + h*8];
            uint4 v = make_uint4(h2u(srow[0],srow[1]), h2u(srow[2],srow[3]),
                                 h2u(srow[4],srow[5]), h2u(srow[6],srow[7]));
            char* panel = (char*)(Out + (((size_t)e*16 + by)*KT2 + (bx*2 + kbl))*(size_t)PANELH);
            uint32_t off = (uint32_t)(m*128) + (uint32_t)((h ^ (m&7))<<4);
            *(uint4*)(panel + off) = v;
        }
    } else {
        float* Out = (float*)OutV;
        const int Nout = NB*BN;
        #pragma unroll
        for (int im=0;im<4;im++)
            #pragma unroll
            for (int rh=0;rh<2;rh++){
                int row = by*BM + wm + im*16 + g + rh*8;
                #pragma unroll
                for (int in=0;in<8;in++){
                    int col = bx*BN + wn + in*8 + 2*t;
                    float v0 = c[im][in][rh*2+0] + __ldg(&bias[col]);
                    float v1 = c[im][in][rh*2+1] + __ldg(&bias[col+1]);
                    *reinterpret_cast<float2*>(&Out[((size_t)e*MTOK + row)*Nout + col]) =
                        make_float2(v0, v1);
                }
            }
    }
}

// ---------------- host ----------------
extern "C" void kernel_launch(void* const* d_in, const int* in_sizes, int n_in,
                              void* d_out, int out_size)
{
    const float* x  = (const float*)d_in[0];   // [E, 2048, 1024]
    const float* w1 = (const float*)d_in[1];   // [E, 1024, 4096]
    const float* w2 = (const float*)d_in[2];   // [E, 4096, 1024]
    const float* b1 = (const float*)d_in[3];   // [4096]
    const float* b2 = (const float*)d_in[4];   // [1024]
    float* out = (float*)d_out;                // [E, 2048, 1024]

    __half *xp, *w1p, *w2p, *hid;
    cudaGetSymbolAddress((void**)&xp,  g_xp);
    cudaGetSymbolAddress((void**)&w1p, g_w1p);
    cudaGetSymbolAddress((void**)&w2p, g_w2p);
    cudaGetSymbolAddress((void**)&hid, g_hid);

    cudaFuncSetAttribute(gemm_t<true>,  cudaFuncAttributeMaxDynamicSharedMemorySize, SMEM_BYTES);
    cudaFuncSetAttribute(gemm_t<false>, cudaFuncAttributeMaxDynamicSharedMemorySize, SMEM_BYTES);

    // pre-pass: fp16 conversion + panelization
    pack_x<<<dim3(DIM/64, MTOK/128, EXPERTS), 256>>>(x, xp);
    pack_w<<<dim3(HID/128, DIM/64, EXPERTS), 256>>>(w1, w1p, DIM, HID);
    pack_w<<<dim3(DIM/128, HID/64, EXPERTS), 256>>>(w2, w2p, HID, DIM);

    // GEMM1 + exact GELU -> hidden fp16 panels; GEMM2 -> row-major fp32 out
    gemm_t<true ><<<dim3(HID/BN, MTOK/BM, EXPERTS), NTHR, SMEM_BYTES>>>(xp, w1p, b1, hid, DIM/64);
    gemm_t<false><<<dim3(DIM/BN, MTOK/BM, EXPERTS), NTHR, SMEM_BYTES>>>(hid, w2p, b2, out, HID/64);
}